// round 16
// baseline (speedup 1.0000x reference)
#include <cuda_runtime.h>
#include <cuda_fp16.h>
#include <math.h>
#include <stdint.h>

// ----------------------------------------------------------------------------
// Problem constants
// ----------------------------------------------------------------------------
#define BATCH 128
#define NTOK  320
#define CH    768
#define NH    12
#define HD    64
#define TMT   64
#define SCALE 0.125f
#define XROWS (BATCH * NTOK)            // 40960

// ----------------------------------------------------------------------------
// Scratch
// ----------------------------------------------------------------------------
__device__ __align__(256) __half g_q[(size_t)BATCH * NH * NTOK * HD];
__device__ __align__(256) __half g_k[(size_t)BATCH * NH * NTOK * HD];
__device__ __align__(256) __half g_v[(size_t)BATCH * NH * NTOK * HD];
__device__ __align__(256) __half g_attn[(size_t)XROWS * CH];
__device__ __align__(256) __half g_x[(size_t)XROWS * CH];
__device__ __align__(256) __half g_wq[(size_t)3 * CH * CH];
__device__ __align__(256) __half g_wp[(size_t)CH * CH];

// ----------------------------------------------------------------------------
// helpers
// ----------------------------------------------------------------------------
__device__ __forceinline__ uint32_t smem_u32(const void* p) {
    uint32_t a;
    asm("{ .reg .u64 t; cvta.to.shared.u64 t, %1; cvt.u32.u64 %0, t; }" : "=r"(a) : "l"(p));
    return a;
}
__device__ __forceinline__ void cpa16(uint32_t saddr, const void* g) {
    asm volatile("cp.async.cg.shared.global [%0], [%1], 16;"
                 :: "r"(saddr), "l"(__cvta_generic_to_global(g)) : "memory");
}
#define CP_COMMIT() asm volatile("cp.async.commit_group;" ::: "memory")
#define CP_WAIT(n)  asm volatile("cp.async.wait_group %0;" :: "n"(n) : "memory")

#define LDSM4(r0, r1, r2, r3, addr) \
    asm volatile("ldmatrix.sync.aligned.m8n8.x4.shared.b16 {%0,%1,%2,%3}, [%4];" \
        : "=r"(r0), "=r"(r1), "=r"(r2), "=r"(r3) : "r"(addr))
#define LDSM4T(r0, r1, r2, r3, addr) \
    asm volatile("ldmatrix.sync.aligned.m8n8.x4.trans.shared.b16 {%0,%1,%2,%3}, [%4];" \
        : "=r"(r0), "=r"(r1), "=r"(r2), "=r"(r3) : "r"(addr))

__device__ __forceinline__ void mma16(float& c0, float& c1, float& c2, float& c3,
                                      uint32_t a0, uint32_t a1, uint32_t a2, uint32_t a3,
                                      uint32_t b0, uint32_t b1) {
    asm volatile(
        "mma.sync.aligned.m16n8k16.row.col.f32.f16.f16.f32 "
        "{%0,%1,%2,%3},{%4,%5,%6,%7},{%8,%9},{%0,%1,%2,%3};"
        : "+f"(c0), "+f"(c1), "+f"(c2), "+f"(c3)
        : "r"(a0), "r"(a1), "r"(a2), "r"(a3), "r"(b0), "r"(b1));
}

// ----------------------------------------------------------------------------
// Prep (merged, validated)
// ----------------------------------------------------------------------------
#define XBLOCKS (XROWS * (CH / 4) / 256)                 // 30720
#define WELEMS  ((3 * CH * CH + CH * CH) / 4)            // 589824
__global__ __launch_bounds__(256) void k_prep(const float* __restrict__ x1,
                                              const float* __restrict__ x2,
                                              const float* __restrict__ qkvw,
                                              const float* __restrict__ projw)
{
    if (blockIdx.x < XBLOCKS) {
        const size_t i = (size_t)blockIdx.x * 256 + threadIdx.x;
        const int row = (int)(i / (CH / 4));
        const int c4 = (int)(i - (size_t)row * (CH / 4));
        const int b = row / NTOK, n = row - b * NTOK;
        const float* src = ((n < TMT) ? x1 : x2) + ((size_t)(b * NTOK + n)) * CH + c4 * 4;
        float4 v = *(const float4*)src;
        __half2 h01 = __floats2half2_rn(v.x, v.y);
        __half2 h23 = __floats2half2_rn(v.z, v.w);
        ((uint2*)g_x)[i] = make_uint2(*(uint32_t*)&h01, *(uint32_t*)&h23);
    } else {
        const size_t i = (size_t)(blockIdx.x - XBLOCKS) * 256 + threadIdx.x;
        const size_t nq = (size_t)3 * CH * CH / 4;
        if (i < nq) {
            float4 v = ((const float4*)qkvw)[i];
            __half2 h01 = __floats2half2_rn(v.x, v.y);
            __half2 h23 = __floats2half2_rn(v.z, v.w);
            ((uint2*)g_wq)[i] = make_uint2(*(uint32_t*)&h01, *(uint32_t*)&h23);
        } else {
            const size_t j = i - nq;
            float4 v = ((const float4*)projw)[j];
            __half2 h01 = __floats2half2_rn(v.x, v.y);
            __half2 h23 = __floats2half2_rn(v.z, v.w);
            ((uint2*)g_wp)[j] = make_uint2(*(uint32_t*)&h01, *(uint32_t*)&h23);
        }
    }
}

// ----------------------------------------------------------------------------
// fp16 GEMM body — K-chunk 64 (128B rows), 12 chunks, 3-stage ring (96KB),
// issue-after-compute.  ldmatrix fragment mapping identical to validated
// rounds 13-15 (128B rows => swizzle term is ^ro, as in the attention tiles).
// ----------------------------------------------------------------------------
__device__ __forceinline__ void gemm_body_f16(
    const __half* __restrict__ aBase,
    const __half* __restrict__ bBase,
    float c[4][4][4], int tid)
{
    extern __shared__ char smem[];
    const uint32_t sbA = smem_u32(smem);            // 3 x 16KB
    const uint32_t sbB = sbA + 49152;               // 3 x 16KB

    const int lane = tid & 31, wid = tid >> 5;
    const int wm = wid & 1, wn = wid >> 1;

    const int m2 = lane >> 3, ro = lane & 7;
    const int rhA8 = (m2 & 1) * 8;
    const uint32_t khA = (uint32_t)(m2 >> 1);
    const int rhB8 = (m2 >> 1) * 8;
    const uint32_t khB = (uint32_t)(m2 & 1);
    uint32_t offA[4];
#pragma unroll
    for (int mi = 0; mi < 4; mi++)
        offA[mi] = (uint32_t)((wm * 64 + mi * 16 + rhA8 + ro) * 128);
    uint32_t offB[2];
#pragma unroll
    for (int j = 0; j < 2; j++)
        offB[j] = (uint32_t)((wn * 32 + j * 16 + rhB8 + ro) * 128);
    const uint32_t ro16 = (uint32_t)ro;

    // writers: thread -> row r = tid>>1, units cu..cu+3 (cu = (tid&1)*4)
    const int wr = tid >> 1, wcu = (tid & 1) * 4;
    uint32_t wOff[4];
#pragma unroll
    for (int j = 0; j < 4; j++)
        wOff[j] = (uint32_t)(wr * 128 + (((wcu + j) ^ (wr & 7)) * 16));
    const __half* aSrc = aBase + (size_t)wr * CH + wcu * 8;
    const __half* bSrc = bBase + (size_t)wr * CH + wcu * 8;

#define ISSUE(cc) do {                                                       \
    const uint32_t _sA = sbA + (uint32_t)((cc) % 3) * 16384;                 \
    const uint32_t _sB = sbB + (uint32_t)((cc) % 3) * 16384;                 \
    const int _ko = (cc) * 64;                                               \
    _Pragma("unroll")                                                        \
    for (int j = 0; j < 4; j++) {                                            \
        cpa16(_sA + wOff[j], aSrc + _ko + j * 8);                            \
        cpa16(_sB + wOff[j], bSrc + _ko + j * 8);                            \
    }                                                                        \
    CP_COMMIT();                                                             \
} while (0)

#define COMPUTE(s) do {                                                      \
    const uint32_t aS = sbA + (uint32_t)(s) * 16384;                         \
    const uint32_t bS = sbB + (uint32_t)(s) * 16384;                         \
    _Pragma("unroll")                                                        \
    for (int ks = 0; ks < 4; ks++) {                                         \
        uint32_t Af[4][4], Bf[4][2];                                         \
        _Pragma("unroll")                                                    \
        for (int mi = 0; mi < 4; mi++)                                       \
            LDSM4(Af[mi][0], Af[mi][1], Af[mi][2], Af[mi][3],                \
                  aS + offA[mi] + ((((uint32_t)(2 * ks) + khA) ^ ro16) * 16)); \
        _Pragma("unroll")                                                    \
        for (int j = 0; j < 2; j++)                                          \
            LDSM4(Bf[2 * j][0], Bf[2 * j][1], Bf[2 * j + 1][0], Bf[2 * j + 1][1], \
                  bS + offB[j] + ((((uint32_t)(2 * ks) + khB) ^ ro16) * 16)); \
        _Pragma("unroll")                                                    \
        for (int mi = 0; mi < 4; mi++)                                       \
            _Pragma("unroll")                                                \
            for (int ni = 0; ni < 4; ni++)                                   \
                mma16(c[mi][ni][0], c[mi][ni][1], c[mi][ni][2], c[mi][ni][3],\
                      Af[mi][0], Af[mi][1], Af[mi][2], Af[mi][3],            \
                      Bf[ni][0], Bf[ni][1]);                                 \
    }                                                                        \
} while (0)

    ISSUE(0); ISSUE(1);
#pragma unroll 1
    for (int ch = 0; ch < 11; ch++) {
        CP_WAIT(1);
        __syncthreads();
        COMPUTE(ch % 3);
        if (ch < 10) ISSUE(ch + 2);
    }
    CP_WAIT(0);
    __syncthreads();
    COMPUTE(11 % 3);
#undef ISSUE
#undef COMPUTE
}

// ----------------------------------------------------------------------------
// Kernel 1: QKV GEMM (validated epilogue)
// ----------------------------------------------------------------------------
__global__ __launch_bounds__(256, 2) void k_qkv_mma()
{
    const int tid = threadIdx.x;
    const int m0 = blockIdx.x * 128, n0 = blockIdx.y * 128;

    float c[4][4][4];
#pragma unroll
    for (int i = 0; i < 4; i++)
#pragma unroll
        for (int j = 0; j < 4; j++)
#pragma unroll
            for (int k = 0; k < 4; k++) c[i][j][k] = 0.f;

    gemm_body_f16(g_x + (size_t)m0 * CH, g_wq + (size_t)n0 * CH, c, tid);

    const int lane = tid & 31, wid = tid >> 5;
    const int wm = wid & 1, wn = wid >> 1;
    const int g = lane >> 2, t = lane & 3;
    const int colw = n0 + wn * 32;
    const int which = colw / CH;
    const int rem = colw - which * CH;
    const int h = rem >> 6;
    const int dbase = rem & 63;
    __half* dst = (which == 0) ? g_q : (which == 1) ? g_k : g_v;

#pragma unroll
    for (int mi = 0; mi < 4; mi++) {
#pragma unroll
        for (int half = 0; half < 2; half++) {
            const int row = m0 + wm * 64 + mi * 16 + g + half * 8;
            const int bb = row / NTOK, nn = row - bb * NTOK;
            __half* p = dst + (((size_t)bb * NH + h) * NTOK + nn) * HD + dbase + 2 * t;
#pragma unroll
            for (int ni = 0; ni < 4; ni++)
                *(__half2*)(p + ni * 8) =
                    __floats2half2_rn(c[mi][ni][half * 2], c[mi][ni][half * 2 + 1]);
        }
    }
}

// ----------------------------------------------------------------------------
// Kernel 3: projection GEMM + bias (validated epilogue)
// ----------------------------------------------------------------------------
__global__ __launch_bounds__(256, 2) void k_proj_mma(const float* __restrict__ bias,
                                                     float* __restrict__ out)
{
    const int tid = threadIdx.x;
    const int m0 = blockIdx.x * 128, n0 = blockIdx.y * 128;

    float c[4][4][4];
#pragma unroll
    for (int i = 0; i < 4; i++)
#pragma unroll
        for (int j = 0; j < 4; j++)
#pragma unroll
            for (int k = 0; k < 4; k++) c[i][j][k] = 0.f;

    gemm_body_f16(g_attn + (size_t)m0 * CH, g_wp + (size_t)n0 * CH, c, tid);

    const int lane = tid & 31, wid = tid >> 5;
    const int wm = wid & 1, wn = wid >> 1;
    const int g = lane >> 2, t = lane & 3;
    const int colb = n0 + wn * 32 + 2 * t;

    float2 bj[4];
#pragma unroll
    for (int ni = 0; ni < 4; ni++)
        bj[ni] = *(const float2*)(bias + colb + ni * 8);

#pragma unroll
    for (int mi = 0; mi < 4; mi++) {
#pragma unroll
        for (int half = 0; half < 2; half++) {
            const int row = m0 + wm * 64 + mi * 16 + g + half * 8;
            float* p = out + (size_t)row * CH + colb;
#pragma unroll
            for (int ni = 0; ni < 4; ni++)
                *(float2*)(p + ni * 8) =
                    make_float2(c[mi][ni][half * 2] + bj[ni].x,
                                c[mi][ni][half * 2 + 1] + bj[ni].y);
        }
    }
}

// ----------------------------------------------------------------------------
// Kernel 2: fp16 flash attention, no max-shift (validated round 15)
// ----------------------------------------------------------------------------
#define SQ_OFF   0
#define SK_OFF   8192
#define SV_OFF   24576
#define SP_OFF   40960
#define PSUM_F   (49152 / 4)
#define SMEM_ATTN 50176

__global__ __launch_bounds__(256, 2) void k_attn_flash()
{
    extern __shared__ char smc[];
    float* smf = (float*)smc;
    const uint32_t sb = smem_u32(smc);

    const int bh = blockIdx.x;
    const int qt = blockIdx.y;
    const int b = bh / NH, h = bh - b * NH;
    const int ktiles = (qt == 0) ? 1 : 5;
    const int ktmax = ktiles - 1;
    const __half* qp = g_q + (size_t)bh * NTOK * HD + (size_t)(qt * 64) * HD;
    const __half* kp = g_k + (size_t)bh * NTOK * HD;
    const __half* vp = g_v + (size_t)bh * NTOK * HD;

    const int tid = threadIdx.x;
    const int lane = tid & 31, wid = tid >> 5;
    const int wm = wid & 1, wn = wid >> 1;
    const int g = lane >> 2, t = lane & 3;

    const int m2 = lane >> 3, ro = lane & 7;
    const int rhA8 = (m2 & 1) * 8;
    const uint32_t khA = (uint32_t)(m2 >> 1);
    const int rhB8 = (m2 >> 1) * 8;
    const uint32_t khB = (uint32_t)(m2 & 1);
    uint32_t offAm[2];
#pragma unroll
    for (int mi = 0; mi < 2; mi++)
        offAm[mi] = (uint32_t)((wm * 32 + mi * 16 + rhA8 + ro) * 128);
    const uint32_t offBr = (uint32_t)((wn * 16 + rhB8 + ro) * 128);
    const uint32_t ro16 = (uint32_t)ro;

    const uint32_t vRow = (uint32_t)(((m2 >> 1) * 8 + ro) * 128);
    uint32_t vUnit[2];
#pragma unroll
    for (int mi = 0; mi < 2; mi++)
        vUnit[mi] = (uint32_t)((((wm * 4 + mi * 2 + (m2 & 1)) ^ ro) * 16));

    const int w_r0 = tid >> 3, w_cu = tid & 7;
    const uint32_t w_phys = (uint32_t)(w_r0 * 128 + ((w_cu ^ (w_r0 & 7)) * 16));

#define ISSUE_T(base, src, tile, buf) do {                                   \
    const uint32_t _d = sb + (base) + (uint32_t)(buf) * 8192;                \
    const __half* _s = (src) + (size_t)((tile) * 64 + w_r0) * HD + w_cu * 8; \
    cpa16(_d + w_phys, _s);                                                  \
    cpa16(_d + w_phys + 4096, _s + 32 * HD);                                 \
    CP_COMMIT();                                                             \
} while (0)

    ISSUE_T(SK_OFF, kp, 0, 0);
    ISSUE_T(SV_OFF, vp, 0, 0);
    ISSUE_T(SK_OFF, kp, (1 < ktmax ? 1 : ktmax), 1);

    {
        const __half* q0 = qp + (size_t)w_r0 * HD + w_cu * 8;
        *(uint4*)(smc + SQ_OFF + w_phys) = *(const uint4*)q0;
        *(uint4*)(smc + SQ_OFF + w_phys + 4096) = *(const uint4*)(q0 + 32 * HD);
    }

    float co[2][2][4];
#pragma unroll
    for (int i = 0; i < 2; i++)
#pragma unroll
        for (int j = 0; j < 2; j++)
#pragma unroll
            for (int k = 0; k < 4; k++) co[i][j][k] = 0.f;
    float rsum[2][2] = {{0.f, 0.f}, {0.f, 0.f}};

#pragma unroll 1
    for (int kt = 0; kt < ktiles; kt++) {
        CP_WAIT(2);
        __syncthreads();
        {
            const int vt = kt + 1;
            ISSUE_T(SV_OFF, vp, (vt < ktmax ? vt : ktmax), vt & 1);
        }

        float cs[2][2][4];
#pragma unroll
        for (int i = 0; i < 2; i++)
#pragma unroll
            for (int j = 0; j < 2; j++)
#pragma unroll
                for (int k = 0; k < 4; k++) cs[i][j][k] = 0.f;

        const uint32_t kbuf = sb + SK_OFF + (uint32_t)((kt & 1) * 8192);
#pragma unroll
        for (int ks = 0; ks < 4; ks++) {
            uint32_t Af[2][4], Bf[2][2];
#pragma unroll
            for (int mi = 0; mi < 2; mi++)
                LDSM4(Af[mi][0], Af[mi][1], Af[mi][2], Af[mi][3],
                      sb + SQ_OFF + offAm[mi] +
                      ((((uint32_t)(2 * ks) + khA) ^ ro16) * 16));
            LDSM4(Bf[0][0], Bf[0][1], Bf[1][0], Bf[1][1],
                  kbuf + offBr + ((((uint32_t)(2 * ks) + khB) ^ ro16) * 16));
#pragma unroll
            for (int mi = 0; mi < 2; mi++)
#pragma unroll
                for (int ni = 0; ni < 2; ni++)
                    mma16(cs[mi][ni][0], cs[mi][ni][1], cs[mi][ni][2], cs[mi][ni][3],
                          Af[mi][0], Af[mi][1], Af[mi][2], Af[mi][3],
                          Bf[ni][0], Bf[ni][1]);
        }

#pragma unroll
        for (int mi = 0; mi < 2; mi++)
#pragma unroll
            for (int half = 0; half < 2; half++) {
                const int q = wm * 32 + mi * 16 + g + half * 8;
#pragma unroll
                for (int ni = 0; ni < 2; ni++) {
                    const float p0 = __expf(cs[mi][ni][half * 2]     * SCALE);
                    const float p1 = __expf(cs[mi][ni][half * 2 + 1] * SCALE);
                    rsum[mi][half] += p0 + p1;
                    *(__half2*)(smc + SP_OFF + q * 128 +
                                (((wn * 2 + ni) ^ g) * 16) + t * 4) =
                        __floats2half2_rn(p0, p1);
                }
            }

        CP_WAIT(2);
        __syncthreads();
        {
            const int nt = kt + 2;
            ISSUE_T(SK_OFF, kp, (nt < ktmax ? nt : ktmax), kt & 1);
        }

        const uint32_t vbuf = sb + SV_OFF + (uint32_t)((kt & 1) * 8192);
#pragma unroll
        for (int ks = 0; ks < 4; ks++) {
            uint32_t Af[2][4], Bf[2][2];
#pragma unroll
            for (int mi = 0; mi < 2; mi++)
                LDSM4T(Af[mi][0], Af[mi][1], Af[mi][2], Af[mi][3],
                       vbuf + (uint32_t)(ks * 2048) + vRow + vUnit[mi]);
            LDSM4(Bf[0][0], Bf[0][1], Bf[1][0], Bf[1][1],
                  sb + SP_OFF + offBr + ((((uint32_t)(2 * ks) + khB) ^ ro16) * 16));
#pragma unroll
            for (int mi = 0; mi < 2; mi++)
#pragma unroll
                for (int ni = 0; ni < 2; ni++)
                    mma16(co[mi][ni][0], co[mi][ni][1], co[mi][ni][2], co[mi][ni][3],
                          Af[mi][0], Af[mi][1], Af[mi][2], Af[mi][3],
                          Bf[ni][0], Bf[ni][1]);
        }
    }

    CP_WAIT(0);
#pragma unroll
    for (int mi = 0; mi < 2; mi++)
#pragma unroll
        for (int half = 0; half < 2; half++) {
            float s = rsum[mi][half];
            s += __shfl_xor_sync(0xffffffffu, s, 1);
            s += __shfl_xor_sync(0xffffffffu, s, 2);
            rsum[mi][half] = s;
        }
    if (t == 0) {
#pragma unroll
        for (int mi = 0; mi < 2; mi++)
#pragma unroll
            for (int half = 0; half < 2; half++)
                smf[PSUM_F + wn * 64 + wm * 32 + mi * 16 + g + half * 8] = rsum[mi][half];
    }
    __syncthreads();

    const int tokbase = b * NTOK + qt * 64;
#pragma unroll
    for (int ni = 0; ni < 2; ni++) {
        const int q0 = wn * 16 + ni * 8 + 2 * t;
        const float l0 = smf[PSUM_F + q0] + smf[PSUM_F + 64 + q0] +
                         smf[PSUM_F + 128 + q0] + smf[PSUM_F + 192 + q0];
        const float l1 = smf[PSUM_F + q0 + 1] + smf[PSUM_F + 64 + q0 + 1] +
                         smf[PSUM_F + 128 + q0 + 1] + smf[PSUM_F + 192 + q0 + 1];
        const float inv0 = 1.f / l0;
        const float inv1 = 1.f / l1;
#pragma unroll
        for (int mi = 0; mi < 2; mi++) {
            const int d0 = wm * 32 + mi * 16 + g;
            __half* p0 = g_attn + (size_t)(tokbase + q0) * CH + h * HD + d0;
            __half* p1 = g_attn + (size_t)(tokbase + q0 + 1) * CH + h * HD + d0;
            p0[0] = __float2half_rn(co[mi][ni][0] * inv0);
            p1[0] = __float2half_rn(co[mi][ni][1] * inv1);
            p0[8] = __float2half_rn(co[mi][ni][2] * inv0);
            p1[8] = __float2half_rn(co[mi][ni][3] * inv1);
        }
    }
#undef ISSUE_T
}

// ----------------------------------------------------------------------------
// Launch
// ----------------------------------------------------------------------------
extern "C" void kernel_launch(void* const* d_in, const int* in_sizes, int n_in,
                              void* d_out, int out_size)
{
    const float* x1     = (const float*)d_in[0];
    const float* x2     = (const float*)d_in[1];
    const float* qkv_w  = (const float*)d_in[2];
    const float* proj_w = (const float*)d_in[3];
    const float* proj_b = (const float*)d_in[4];
    float* out = (float*)d_out;

    const int smem_gemm = 98304;                   // 3-stage x (16K A + 16K B)
    cudaFuncSetAttribute(k_attn_flash, cudaFuncAttributeMaxDynamicSharedMemorySize, SMEM_ATTN);
    cudaFuncSetAttribute(k_qkv_mma,    cudaFuncAttributeMaxDynamicSharedMemorySize, smem_gemm);
    cudaFuncSetAttribute(k_proj_mma,   cudaFuncAttributeMaxDynamicSharedMemorySize, smem_gemm);

    k_prep<<<XBLOCKS + WELEMS / 256, 256>>>(x1, x2, qkv_w, proj_w);

    dim3 g1(XROWS / 128, 3 * CH / 128);                            // (320, 18)
    k_qkv_mma<<<g1, 256, smem_gemm>>>();

    dim3 g2(BATCH * NH, NTOK / 64);                                // (1536, 5)
    k_attn_flash<<<g2, 256, SMEM_ATTN>>>();

    dim3 g3(XROWS / 128, CH / 128);                                // (320, 6)
    k_proj_mma<<<g3, 256, smem_gemm>>>(proj_b, out);
}

// round 17
// speedup vs baseline: 1.0001x; 1.0001x over previous
#include <cuda_runtime.h>
#include <cuda_fp16.h>
#include <math.h>
#include <stdint.h>

// ----------------------------------------------------------------------------
// Problem constants
// ----------------------------------------------------------------------------
#define BATCH 128
#define NTOK  320
#define CH    768
#define NH    12
#define HD    64
#define TMT   64
#define SCALE 0.125f
#define XROWS (BATCH * NTOK)            // 40960

// ----------------------------------------------------------------------------
// Scratch
// ----------------------------------------------------------------------------
__device__ __align__(256) __half g_q[(size_t)BATCH * NH * NTOK * HD];
__device__ __align__(256) __half g_k[(size_t)BATCH * NH * NTOK * HD];
__device__ __align__(256) __half g_v[(size_t)BATCH * NH * NTOK * HD];
__device__ __align__(256) __half g_attn[(size_t)XROWS * CH];
__device__ __align__(256) __half g_x[(size_t)XROWS * CH];
__device__ __align__(256) __half g_wq[(size_t)3 * CH * CH];
__device__ __align__(256) __half g_wp[(size_t)CH * CH];

// ----------------------------------------------------------------------------
// helpers
// ----------------------------------------------------------------------------
__device__ __forceinline__ uint32_t smem_u32(const void* p) {
    uint32_t a;
    asm("{ .reg .u64 t; cvta.to.shared.u64 t, %1; cvt.u32.u64 %0, t; }" : "=r"(a) : "l"(p));
    return a;
}
__device__ __forceinline__ void cpa16(uint32_t saddr, const void* g) {
    asm volatile("cp.async.cg.shared.global [%0], [%1], 16;"
                 :: "r"(saddr), "l"(__cvta_generic_to_global(g)) : "memory");
}
#define CP_COMMIT() asm volatile("cp.async.commit_group;" ::: "memory")
#define CP_WAIT(n)  asm volatile("cp.async.wait_group %0;" :: "n"(n) : "memory")

#define LDSM4(r0, r1, r2, r3, addr) \
    asm volatile("ldmatrix.sync.aligned.m8n8.x4.shared.b16 {%0,%1,%2,%3}, [%4];" \
        : "=r"(r0), "=r"(r1), "=r"(r2), "=r"(r3) : "r"(addr))
#define LDSM4T(r0, r1, r2, r3, addr) \
    asm volatile("ldmatrix.sync.aligned.m8n8.x4.trans.shared.b16 {%0,%1,%2,%3}, [%4];" \
        : "=r"(r0), "=r"(r1), "=r"(r2), "=r"(r3) : "r"(addr))

__device__ __forceinline__ void mma16(float& c0, float& c1, float& c2, float& c3,
                                      uint32_t a0, uint32_t a1, uint32_t a2, uint32_t a3,
                                      uint32_t b0, uint32_t b1) {
    asm volatile(
        "mma.sync.aligned.m16n8k16.row.col.f32.f16.f16.f32 "
        "{%0,%1,%2,%3},{%4,%5,%6,%7},{%8,%9},{%0,%1,%2,%3};"
        : "+f"(c0), "+f"(c1), "+f"(c2), "+f"(c3)
        : "r"(a0), "r"(a1), "r"(a2), "r"(a3), "r"(b0), "r"(b1));
}

// ----------------------------------------------------------------------------
// Prep (merged, validated)
// ----------------------------------------------------------------------------
#define XBLOCKS (XROWS * (CH / 4) / 256)                 // 30720
#define WELEMS  ((3 * CH * CH + CH * CH) / 4)            // 589824
__global__ __launch_bounds__(256) void k_prep(const float* __restrict__ x1,
                                              const float* __restrict__ x2,
                                              const float* __restrict__ qkvw,
                                              const float* __restrict__ projw)
{
    if (blockIdx.x < XBLOCKS) {
        const size_t i = (size_t)blockIdx.x * 256 + threadIdx.x;
        const int row = (int)(i / (CH / 4));
        const int c4 = (int)(i - (size_t)row * (CH / 4));
        const int b = row / NTOK, n = row - b * NTOK;
        const float* src = ((n < TMT) ? x1 : x2) + ((size_t)(b * NTOK + n)) * CH + c4 * 4;
        float4 v = *(const float4*)src;
        __half2 h01 = __floats2half2_rn(v.x, v.y);
        __half2 h23 = __floats2half2_rn(v.z, v.w);
        ((uint2*)g_x)[i] = make_uint2(*(uint32_t*)&h01, *(uint32_t*)&h23);
    } else {
        const size_t i = (size_t)(blockIdx.x - XBLOCKS) * 256 + threadIdx.x;
        const size_t nq = (size_t)3 * CH * CH / 4;
        if (i < nq) {
            float4 v = ((const float4*)qkvw)[i];
            __half2 h01 = __floats2half2_rn(v.x, v.y);
            __half2 h23 = __floats2half2_rn(v.z, v.w);
            ((uint2*)g_wq)[i] = make_uint2(*(uint32_t*)&h01, *(uint32_t*)&h23);
        } else {
            const size_t j = i - nq;
            float4 v = ((const float4*)projw)[j];
            __half2 h01 = __floats2half2_rn(v.x, v.y);
            __half2 h23 = __floats2half2_rn(v.z, v.w);
            ((uint2*)g_wp)[j] = make_uint2(*(uint32_t*)&h01, *(uint32_t*)&h23);
        }
    }
}

// ----------------------------------------------------------------------------
// fp16 GEMM body — K-chunk 64 (128B rows), 12 chunks, 3-stage ring (96KB),
// issue-after-compute.  ldmatrix fragment mapping identical to validated
// rounds 13-15 (128B rows => swizzle term is ^ro, as in the attention tiles).
// ----------------------------------------------------------------------------
__device__ __forceinline__ void gemm_body_f16(
    const __half* __restrict__ aBase,
    const __half* __restrict__ bBase,
    float c[4][4][4], int tid)
{
    extern __shared__ char smem[];
    const uint32_t sbA = smem_u32(smem);            // 3 x 16KB
    const uint32_t sbB = sbA + 49152;               // 3 x 16KB

    const int lane = tid & 31, wid = tid >> 5;
    const int wm = wid & 1, wn = wid >> 1;

    const int m2 = lane >> 3, ro = lane & 7;
    const int rhA8 = (m2 & 1) * 8;
    const uint32_t khA = (uint32_t)(m2 >> 1);
    const int rhB8 = (m2 >> 1) * 8;
    const uint32_t khB = (uint32_t)(m2 & 1);
    uint32_t offA[4];
#pragma unroll
    for (int mi = 0; mi < 4; mi++)
        offA[mi] = (uint32_t)((wm * 64 + mi * 16 + rhA8 + ro) * 128);
    uint32_t offB[2];
#pragma unroll
    for (int j = 0; j < 2; j++)
        offB[j] = (uint32_t)((wn * 32 + j * 16 + rhB8 + ro) * 128);
    const uint32_t ro16 = (uint32_t)ro;

    // writers: thread -> row r = tid>>1, units cu..cu+3 (cu = (tid&1)*4)
    const int wr = tid >> 1, wcu = (tid & 1) * 4;
    uint32_t wOff[4];
#pragma unroll
    for (int j = 0; j < 4; j++)
        wOff[j] = (uint32_t)(wr * 128 + (((wcu + j) ^ (wr & 7)) * 16));
    const __half* aSrc = aBase + (size_t)wr * CH + wcu * 8;
    const __half* bSrc = bBase + (size_t)wr * CH + wcu * 8;

#define ISSUE(cc) do {                                                       \
    const uint32_t _sA = sbA + (uint32_t)((cc) % 3) * 16384;                 \
    const uint32_t _sB = sbB + (uint32_t)((cc) % 3) * 16384;                 \
    const int _ko = (cc) * 64;                                               \
    _Pragma("unroll")                                                        \
    for (int j = 0; j < 4; j++) {                                            \
        cpa16(_sA + wOff[j], aSrc + _ko + j * 8);                            \
        cpa16(_sB + wOff[j], bSrc + _ko + j * 8);                            \
    }                                                                        \
    CP_COMMIT();                                                             \
} while (0)

#define COMPUTE(s) do {                                                      \
    const uint32_t aS = sbA + (uint32_t)(s) * 16384;                         \
    const uint32_t bS = sbB + (uint32_t)(s) * 16384;                         \
    _Pragma("unroll")                                                        \
    for (int ks = 0; ks < 4; ks++) {                                         \
        uint32_t Af[4][4], Bf[4][2];                                         \
        _Pragma("unroll")                                                    \
        for (int mi = 0; mi < 4; mi++)                                       \
            LDSM4(Af[mi][0], Af[mi][1], Af[mi][2], Af[mi][3],                \
                  aS + offA[mi] + ((((uint32_t)(2 * ks) + khA) ^ ro16) * 16)); \
        _Pragma("unroll")                                                    \
        for (int j = 0; j < 2; j++)                                          \
            LDSM4(Bf[2 * j][0], Bf[2 * j][1], Bf[2 * j + 1][0], Bf[2 * j + 1][1], \
                  bS + offB[j] + ((((uint32_t)(2 * ks) + khB) ^ ro16) * 16)); \
        _Pragma("unroll")                                                    \
        for (int mi = 0; mi < 4; mi++)                                       \
            _Pragma("unroll")                                                \
            for (int ni = 0; ni < 4; ni++)                                   \
                mma16(c[mi][ni][0], c[mi][ni][1], c[mi][ni][2], c[mi][ni][3],\
                      Af[mi][0], Af[mi][1], Af[mi][2], Af[mi][3],            \
                      Bf[ni][0], Bf[ni][1]);                                 \
    }                                                                        \
} while (0)

    ISSUE(0); ISSUE(1);
#pragma unroll 1
    for (int ch = 0; ch < 11; ch++) {
        CP_WAIT(1);
        __syncthreads();
        COMPUTE(ch % 3);
        if (ch < 10) ISSUE(ch + 2);
    }
    CP_WAIT(0);
    __syncthreads();
    COMPUTE(11 % 3);
#undef ISSUE
#undef COMPUTE
}

// ----------------------------------------------------------------------------
// Kernel 1: QKV GEMM (validated epilogue)
// ----------------------------------------------------------------------------
__global__ __launch_bounds__(256, 2) void k_qkv_mma()
{
    const int tid = threadIdx.x;
    const int m0 = blockIdx.x * 128, n0 = blockIdx.y * 128;

    float c[4][4][4];
#pragma unroll
    for (int i = 0; i < 4; i++)
#pragma unroll
        for (int j = 0; j < 4; j++)
#pragma unroll
            for (int k = 0; k < 4; k++) c[i][j][k] = 0.f;

    gemm_body_f16(g_x + (size_t)m0 * CH, g_wq + (size_t)n0 * CH, c, tid);

    const int lane = tid & 31, wid = tid >> 5;
    const int wm = wid & 1, wn = wid >> 1;
    const int g = lane >> 2, t = lane & 3;
    const int colw = n0 + wn * 32;
    const int which = colw / CH;
    const int rem = colw - which * CH;
    const int h = rem >> 6;
    const int dbase = rem & 63;
    __half* dst = (which == 0) ? g_q : (which == 1) ? g_k : g_v;

#pragma unroll
    for (int mi = 0; mi < 4; mi++) {
#pragma unroll
        for (int half = 0; half < 2; half++) {
            const int row = m0 + wm * 64 + mi * 16 + g + half * 8;
            const int bb = row / NTOK, nn = row - bb * NTOK;
            __half* p = dst + (((size_t)bb * NH + h) * NTOK + nn) * HD + dbase + 2 * t;
#pragma unroll
            for (int ni = 0; ni < 4; ni++)
                *(__half2*)(p + ni * 8) =
                    __floats2half2_rn(c[mi][ni][half * 2], c[mi][ni][half * 2 + 1]);
        }
    }
}

// ----------------------------------------------------------------------------
// Kernel 3: projection GEMM + bias (validated epilogue)
// ----------------------------------------------------------------------------
__global__ __launch_bounds__(256, 2) void k_proj_mma(const float* __restrict__ bias,
                                                     float* __restrict__ out)
{
    const int tid = threadIdx.x;
    const int m0 = blockIdx.x * 128, n0 = blockIdx.y * 128;

    float c[4][4][4];
#pragma unroll
    for (int i = 0; i < 4; i++)
#pragma unroll
        for (int j = 0; j < 4; j++)
#pragma unroll
            for (int k = 0; k < 4; k++) c[i][j][k] = 0.f;

    gemm_body_f16(g_attn + (size_t)m0 * CH, g_wp + (size_t)n0 * CH, c, tid);

    const int lane = tid & 31, wid = tid >> 5;
    const int wm = wid & 1, wn = wid >> 1;
    const int g = lane >> 2, t = lane & 3;
    const int colb = n0 + wn * 32 + 2 * t;

    float2 bj[4];
#pragma unroll
    for (int ni = 0; ni < 4; ni++)
        bj[ni] = *(const float2*)(bias + colb + ni * 8);

#pragma unroll
    for (int mi = 0; mi < 4; mi++) {
#pragma unroll
        for (int half = 0; half < 2; half++) {
            const int row = m0 + wm * 64 + mi * 16 + g + half * 8;
            float* p = out + (size_t)row * CH + colb;
#pragma unroll
            for (int ni = 0; ni < 4; ni++)
                *(float2*)(p + ni * 8) =
                    make_float2(c[mi][ni][half * 2] + bj[ni].x,
                                c[mi][ni][half * 2 + 1] + bj[ni].y);
        }
    }
}

// ----------------------------------------------------------------------------
// Kernel 2: fp16 flash attention, no max-shift (validated round 15)
// ----------------------------------------------------------------------------
#define SQ_OFF   0
#define SK_OFF   8192
#define SV_OFF   24576
#define SP_OFF   40960
#define PSUM_F   (49152 / 4)
#define SMEM_ATTN 50176

__global__ __launch_bounds__(256, 2) void k_attn_flash()
{
    extern __shared__ char smc[];
    float* smf = (float*)smc;
    const uint32_t sb = smem_u32(smc);

    const int bh = blockIdx.x;
    const int qt = blockIdx.y;
    const int b = bh / NH, h = bh - b * NH;
    const int ktiles = (qt == 0) ? 1 : 5;
    const int ktmax = ktiles - 1;
    const __half* qp = g_q + (size_t)bh * NTOK * HD + (size_t)(qt * 64) * HD;
    const __half* kp = g_k + (size_t)bh * NTOK * HD;
    const __half* vp = g_v + (size_t)bh * NTOK * HD;

    const int tid = threadIdx.x;
    const int lane = tid & 31, wid = tid >> 5;
    const int wm = wid & 1, wn = wid >> 1;
    const int g = lane >> 2, t = lane & 3;

    const int m2 = lane >> 3, ro = lane & 7;
    const int rhA8 = (m2 & 1) * 8;
    const uint32_t khA = (uint32_t)(m2 >> 1);
    const int rhB8 = (m2 >> 1) * 8;
    const uint32_t khB = (uint32_t)(m2 & 1);
    uint32_t offAm[2];
#pragma unroll
    for (int mi = 0; mi < 2; mi++)
        offAm[mi] = (uint32_t)((wm * 32 + mi * 16 + rhA8 + ro) * 128);
    const uint32_t offBr = (uint32_t)((wn * 16 + rhB8 + ro) * 128);
    const uint32_t ro16 = (uint32_t)ro;

    const uint32_t vRow = (uint32_t)(((m2 >> 1) * 8 + ro) * 128);
    uint32_t vUnit[2];
#pragma unroll
    for (int mi = 0; mi < 2; mi++)
        vUnit[mi] = (uint32_t)((((wm * 4 + mi * 2 + (m2 & 1)) ^ ro) * 16));

    const int w_r0 = tid >> 3, w_cu = tid & 7;
    const uint32_t w_phys = (uint32_t)(w_r0 * 128 + ((w_cu ^ (w_r0 & 7)) * 16));

#define ISSUE_T(base, src, tile, buf) do {                                   \
    const uint32_t _d = sb + (base) + (uint32_t)(buf) * 8192;                \
    const __half* _s = (src) + (size_t)((tile) * 64 + w_r0) * HD + w_cu * 8; \
    cpa16(_d + w_phys, _s);                                                  \
    cpa16(_d + w_phys + 4096, _s + 32 * HD);                                 \
    CP_COMMIT();                                                             \
} while (0)

    ISSUE_T(SK_OFF, kp, 0, 0);
    ISSUE_T(SV_OFF, vp, 0, 0);
    ISSUE_T(SK_OFF, kp, (1 < ktmax ? 1 : ktmax), 1);

    {
        const __half* q0 = qp + (size_t)w_r0 * HD + w_cu * 8;
        *(uint4*)(smc + SQ_OFF + w_phys) = *(const uint4*)q0;
        *(uint4*)(smc + SQ_OFF + w_phys + 4096) = *(const uint4*)(q0 + 32 * HD);
    }

    float co[2][2][4];
#pragma unroll
    for (int i = 0; i < 2; i++)
#pragma unroll
        for (int j = 0; j < 2; j++)
#pragma unroll
            for (int k = 0; k < 4; k++) co[i][j][k] = 0.f;
    float rsum[2][2] = {{0.f, 0.f}, {0.f, 0.f}};

#pragma unroll 1
    for (int kt = 0; kt < ktiles; kt++) {
        CP_WAIT(2);
        __syncthreads();
        {
            const int vt = kt + 1;
            ISSUE_T(SV_OFF, vp, (vt < ktmax ? vt : ktmax), vt & 1);
        }

        float cs[2][2][4];
#pragma unroll
        for (int i = 0; i < 2; i++)
#pragma unroll
            for (int j = 0; j < 2; j++)
#pragma unroll
                for (int k = 0; k < 4; k++) cs[i][j][k] = 0.f;

        const uint32_t kbuf = sb + SK_OFF + (uint32_t)((kt & 1) * 8192);
#pragma unroll
        for (int ks = 0; ks < 4; ks++) {
            uint32_t Af[2][4], Bf[2][2];
#pragma unroll
            for (int mi = 0; mi < 2; mi++)
                LDSM4(Af[mi][0], Af[mi][1], Af[mi][2], Af[mi][3],
                      sb + SQ_OFF + offAm[mi] +
                      ((((uint32_t)(2 * ks) + khA) ^ ro16) * 16));
            LDSM4(Bf[0][0], Bf[0][1], Bf[1][0], Bf[1][1],
                  kbuf + offBr + ((((uint32_t)(2 * ks) + khB) ^ ro16) * 16));
#pragma unroll
            for (int mi = 0; mi < 2; mi++)
#pragma unroll
                for (int ni = 0; ni < 2; ni++)
                    mma16(cs[mi][ni][0], cs[mi][ni][1], cs[mi][ni][2], cs[mi][ni][3],
                          Af[mi][0], Af[mi][1], Af[mi][2], Af[mi][3],
                          Bf[ni][0], Bf[ni][1]);
        }

#pragma unroll
        for (int mi = 0; mi < 2; mi++)
#pragma unroll
            for (int half = 0; half < 2; half++) {
                const int q = wm * 32 + mi * 16 + g + half * 8;
#pragma unroll
                for (int ni = 0; ni < 2; ni++) {
                    const float p0 = __expf(cs[mi][ni][half * 2]     * SCALE);
                    const float p1 = __expf(cs[mi][ni][half * 2 + 1] * SCALE);
                    rsum[mi][half] += p0 + p1;
                    *(__half2*)(smc + SP_OFF + q * 128 +
                                (((wn * 2 + ni) ^ g) * 16) + t * 4) =
                        __floats2half2_rn(p0, p1);
                }
            }

        CP_WAIT(2);
        __syncthreads();
        {
            const int nt = kt + 2;
            ISSUE_T(SK_OFF, kp, (nt < ktmax ? nt : ktmax), kt & 1);
        }

        const uint32_t vbuf = sb + SV_OFF + (uint32_t)((kt & 1) * 8192);
#pragma unroll
        for (int ks = 0; ks < 4; ks++) {
            uint32_t Af[2][4], Bf[2][2];
#pragma unroll
            for (int mi = 0; mi < 2; mi++)
                LDSM4T(Af[mi][0], Af[mi][1], Af[mi][2], Af[mi][3],
                       vbuf + (uint32_t)(ks * 2048) + vRow + vUnit[mi]);
            LDSM4(Bf[0][0], Bf[0][1], Bf[1][0], Bf[1][1],
                  sb + SP_OFF + offBr + ((((uint32_t)(2 * ks) + khB) ^ ro16) * 16));
#pragma unroll
            for (int mi = 0; mi < 2; mi++)
#pragma unroll
                for (int ni = 0; ni < 2; ni++)
                    mma16(co[mi][ni][0], co[mi][ni][1], co[mi][ni][2], co[mi][ni][3],
                          Af[mi][0], Af[mi][1], Af[mi][2], Af[mi][3],
                          Bf[ni][0], Bf[ni][1]);
        }
    }

    CP_WAIT(0);
#pragma unroll
    for (int mi = 0; mi < 2; mi++)
#pragma unroll
        for (int half = 0; half < 2; half++) {
            float s = rsum[mi][half];
            s += __shfl_xor_sync(0xffffffffu, s, 1);
            s += __shfl_xor_sync(0xffffffffu, s, 2);
            rsum[mi][half] = s;
        }
    if (t == 0) {
#pragma unroll
        for (int mi = 0; mi < 2; mi++)
#pragma unroll
            for (int half = 0; half < 2; half++)
                smf[PSUM_F + wn * 64 + wm * 32 + mi * 16 + g + half * 8] = rsum[mi][half];
    }
    __syncthreads();

    const int tokbase = b * NTOK + qt * 64;
#pragma unroll
    for (int ni = 0; ni < 2; ni++) {
        const int q0 = wn * 16 + ni * 8 + 2 * t;
        const float l0 = smf[PSUM_F + q0] + smf[PSUM_F + 64 + q0] +
                         smf[PSUM_F + 128 + q0] + smf[PSUM_F + 192 + q0];
        const float l1 = smf[PSUM_F + q0 + 1] + smf[PSUM_F + 64 + q0 + 1] +
                         smf[PSUM_F + 128 + q0 + 1] + smf[PSUM_F + 192 + q0 + 1];
        const float inv0 = 1.f / l0;
        const float inv1 = 1.f / l1;
#pragma unroll
        for (int mi = 0; mi < 2; mi++) {
            const int d0 = wm * 32 + mi * 16 + g;
            __half* p0 = g_attn + (size_t)(tokbase + q0) * CH + h * HD + d0;
            __half* p1 = g_attn + (size_t)(tokbase + q0 + 1) * CH + h * HD + d0;
            p0[0] = __float2half_rn(co[mi][ni][0] * inv0);
            p1[0] = __float2half_rn(co[mi][ni][1] * inv1);
            p0[8] = __float2half_rn(co[mi][ni][2] * inv0);
            p1[8] = __float2half_rn(co[mi][ni][3] * inv1);
        }
    }
#undef ISSUE_T
}

// ----------------------------------------------------------------------------
// Launch
// ----------------------------------------------------------------------------
extern "C" void kernel_launch(void* const* d_in, const int* in_sizes, int n_in,
                              void* d_out, int out_size)
{
    const float* x1     = (const float*)d_in[0];
    const float* x2     = (const float*)d_in[1];
    const float* qkv_w  = (const float*)d_in[2];
    const float* proj_w = (const float*)d_in[3];
    const float* proj_b = (const float*)d_in[4];
    float* out = (float*)d_out;

    const int smem_gemm = 98304;                   // 3-stage x (16K A + 16K B)
    cudaFuncSetAttribute(k_attn_flash, cudaFuncAttributeMaxDynamicSharedMemorySize, SMEM_ATTN);
    cudaFuncSetAttribute(k_qkv_mma,    cudaFuncAttributeMaxDynamicSharedMemorySize, smem_gemm);
    cudaFuncSetAttribute(k_proj_mma,   cudaFuncAttributeMaxDynamicSharedMemorySize, smem_gemm);

    k_prep<<<XBLOCKS + WELEMS / 256, 256>>>(x1, x2, qkv_w, proj_w);

    dim3 g1(XROWS / 128, 3 * CH / 128);                            // (320, 18)
    k_qkv_mma<<<g1, 256, smem_gemm>>>();

    dim3 g2(BATCH * NH, NTOK / 64);                                // (1536, 5)
    k_attn_flash<<<g2, 256, SMEM_ATTN>>>();

    dim3 g3(XROWS / 128, CH / 128);                                // (320, 6)
    k_proj_mma<<<g3, 256, smem_gemm>>>(proj_b, out);
}